// round 11
// baseline (speedup 1.0000x reference)
#include <cuda_runtime.h>
#include <cuda_bf16.h>
#include <math_constants.h>

#define B_      8
#define N_      8192
#define S_      2048
#define K_      16
#define DIN_    64
#define DOUT_   128
#define BN_EPS_ 1e-5f

#define FT_     1024           // FPS threads (32 warps)
#define PPT_    8              // points per thread; warp owns 256 Morton pts
#define NCELL_  4096           // 16x16x16 spatial cells, Morton-ordered

// ---------------- scratch (static __device__ — no allocation allowed) ----------------
__device__ int   g_fps_idx[B_ * S_];
__device__ int   g_knn_idx[B_ * S_ * K_];
__device__ float g_h[B_ * N_ * DOUT_];   // 33.5 MB, post MLP+BN+ReLU features

// 4-bit Morton spread: bits -> positions 0,3,6,9 (setup only)
__device__ __forceinline__ unsigned spread3(unsigned v) {
    return (v & 1u) | ((v & 2u) << 2) | ((v & 4u) << 4) | ((v & 8u) << 6);
}

// ============================================================================
// 1) FPS — one CTA per batch, 1024 threads, WARP-UNIFORM exact pruning.
//    Morton counting sort (16^3 cells) -> warp w owns 256 spatially-compact
//    points (sorted slots 256w..256w+255); warp bbox butterfly-reduced at
//    setup and register-replicated.
//    Iteration (one barrier, double-buffered slots):
//      - warp-uniform check: lb(c, warp bbox)*0.99999 >= m_wc (cached warp
//        max pd) => EVERY point's update is provably a bit-exact no-op ->
//        whole warp skips (no divergence); lane0 re-emits cached slot.
//      - else: per-thread smem recompute (exact IEEE __fsub/__fmul/__fadd,
//        ((x+y)+z)), local argmax with ORIGINAL-index tie-break, warp REDUX,
//        owner broadcasts winner coords (ballot+shfl), cache updated.
//      - BAR; every warp reduces the 32 slots; cross-warp tie-break via
//        packed (idx<<5|slot) REDUX-min; winner coords = one LDS.128.
//    Ties -> smallest original index everywhere == jnp.argmax semantics.
// ============================================================================
extern __shared__ float4 s_sort[];   // [N_] sorted coords, orig idx in .w (128 KB)

__global__ __launch_bounds__(FT_, 1)
void fps_kernel(const float* __restrict__ coords, float* __restrict__ out_coords)
{
    __shared__ unsigned s_hist[NCELL_];          // 16 KB
    __shared__ unsigned s_wsum[32];
    __shared__ unsigned s_val[2][32];
    __shared__ unsigned s_idx[2][32];
    __shared__ float4   s_cxyz[2][32];

    const int b    = blockIdx.x;
    const int t    = threadIdx.x;
    const int lane = t & 31;
    const int w    = t >> 5;
    const unsigned FULL = 0xffffffffu;
    const float* cb = coords + (size_t)b * N_ * 3;

    // ---------------- setup: Morton counting sort ----------------
    for (int v = t; v < NCELL_; v += FT_) s_hist[v] = 0u;
    __syncthreads();

    float f[24];
    unsigned cells[PPT_];
    {
        const float4* src = (const float4*)(cb + t * 24);   // points 8t..8t+7
#pragma unroll
        for (int q = 0; q < 6; q++) {
            float4 v = src[q];
            f[q * 4 + 0] = v.x; f[q * 4 + 1] = v.y; f[q * 4 + 2] = v.z; f[q * 4 + 3] = v.w;
        }
#pragma unroll
        for (int j = 0; j < PPT_; j++) {
            unsigned bx = (unsigned)min(max((int)floorf(f[3 * j + 0] * 2.0f) + 8, 0), 15);
            unsigned by = (unsigned)min(max((int)floorf(f[3 * j + 1] * 2.0f) + 8, 0), 15);
            unsigned bz = (unsigned)min(max((int)floorf(f[3 * j + 2] * 2.0f) + 8, 0), 15);
            cells[j] = spread3(bx) | (spread3(by) << 1) | (spread3(bz) << 2);
            atomicAdd(&s_hist[cells[j]], 1u);
        }
    }
    __syncthreads();
    // parallel exclusive scan of 4096 counters (each thread owns 4)
    {
        unsigned a0 = s_hist[t * 4 + 0], a1 = s_hist[t * 4 + 1];
        unsigned a2 = s_hist[t * 4 + 2], a3 = s_hist[t * 4 + 3];
        unsigned tot = a0 + a1 + a2 + a3;
        unsigned inc = tot;
#pragma unroll
        for (int off = 1; off < 32; off <<= 1) {
            unsigned u = __shfl_up_sync(FULL, inc, off);
            if (lane >= off) inc += u;
        }
        if (lane == 31) s_wsum[w] = inc;
        unsigned exl = inc - tot;
        __syncthreads();
        if (t < 32) {
            unsigned v = s_wsum[t];
            unsigned i2 = v;
#pragma unroll
            for (int off = 1; off < 32; off <<= 1) {
                unsigned u = __shfl_up_sync(FULL, i2, off);
                if (lane >= off) i2 += u;
            }
            s_wsum[t] = i2 - v;
        }
        __syncthreads();
        unsigned base = s_wsum[w] + exl;
        s_hist[t * 4 + 0] = base;
        s_hist[t * 4 + 1] = base + a0;
        s_hist[t * 4 + 2] = base + a0 + a1;
        s_hist[t * 4 + 3] = base + a0 + a1 + a2;
    }
    __syncthreads();
#pragma unroll
    for (int j = 0; j < PPT_; j++) {
        unsigned dst = atomicAdd(&s_hist[cells[j]], 1u);
        unsigned orig = (unsigned)(t * PPT_ + j);
        s_sort[dst] = make_float4(f[3 * j], f[3 * j + 1], f[3 * j + 2],
                                  __uint_as_float(orig));
    }
    __syncthreads();

    // ---- per-thread pd init + thread bbox -> warp bbox (butterfly) ----
    float pd[PPT_];
    float bmnx = CUDART_INF_F, bmny = CUDART_INF_F, bmnz = CUDART_INF_F;
    float bmxx = -CUDART_INF_F, bmxy = -CUDART_INF_F, bmxz = -CUDART_INF_F;
    {
        const int base = t * PPT_;
#pragma unroll
        for (int j = 0; j < PPT_; j++) {
            float4 p4 = s_sort[base + j];
            bmnx = fminf(bmnx, p4.x); bmxx = fmaxf(bmxx, p4.x);
            bmny = fminf(bmny, p4.y); bmxy = fmaxf(bmxy, p4.y);
            bmnz = fminf(bmnz, p4.z); bmxz = fmaxf(bmxz, p4.z);
            pd[j] = 1e10f;
        }
#pragma unroll
        for (int off = 16; off > 0; off >>= 1) {
            bmnx = fminf(bmnx, __shfl_xor_sync(FULL, bmnx, off));
            bmny = fminf(bmny, __shfl_xor_sync(FULL, bmny, off));
            bmnz = fminf(bmnz, __shfl_xor_sync(FULL, bmnz, off));
            bmxx = fmaxf(bmxx, __shfl_xor_sync(FULL, bmxx, off));
            bmxy = fmaxf(bmxy, __shfl_xor_sync(FULL, bmxy, off));
            bmxz = fmaxf(bmxz, __shfl_xor_sync(FULL, bmxz, off));
        }
    }

    // cached warp winner (register-replicated across the warp)
    float    m_wc  = CUDART_INF_F;     // cached warp max pd (forces 1st compute)
    unsigned wm_c  = 0x7F800000u;      // its float bits
    unsigned wmi_c = 0xffffffffu;      // cached warp argmax original index
    float    cwx = 0.f, cwy = 0.f, cwz = 0.f;  // cached winner coords

    unsigned g = 0u;
    float4 c = make_float4(cb[0], cb[1], cb[2], 0.0f);   // start at point 0

    for (int i = 0; i < S_; i++) {
        if (t == 0) {
            g_fps_idx[b * S_ + i] = (int)g;
            float* oc = out_coords + ((size_t)b * S_ + i) * 3;
            oc[0] = c.x; oc[1] = c.y; oc[2] = c.z;
        }
        if (i == S_ - 1) break;
        const int buf = i & 1;

        // ---- WARP-UNIFORM bound check (identical on all lanes) ----
        float ax = fmaxf(fmaxf(__fsub_rn(bmnx, c.x), __fsub_rn(c.x, bmxx)), 0.0f);
        float ay = fmaxf(fmaxf(__fsub_rn(bmny, c.y), __fsub_rn(c.y, bmxy)), 0.0f);
        float az = fmaxf(fmaxf(__fsub_rn(bmnz, c.z), __fsub_rn(c.z, bmxz)), 0.0f);
        float lb = ax * ax + ay * ay + az * az;

        if (!(lb * 0.99999f >= m_wc)) {
            // ---- compute path: per-thread smem recompute + argmax ----
            const int base = t * PPT_;
            float nm = -CUDART_INF_F; unsigned nmi = 0xffffffffu;
            float nx = 0.f, ny = 0.f, nz = 0.f;
#pragma unroll
            for (int j = 0; j < PPT_; j++) {
                float4 p4 = s_sort[base + j];
                float dx = __fsub_rn(p4.x, c.x);
                float dy = __fsub_rn(p4.y, c.y);
                float dz = __fsub_rn(p4.z, c.z);
                float dd = __fadd_rn(__fadd_rn(__fmul_rn(dx, dx), __fmul_rn(dy, dy)),
                                     __fmul_rn(dz, dz));
                float pdj = fminf(pd[j], dd);
                pd[j] = pdj;
                unsigned og = __float_as_uint(p4.w);
                if (pdj > nm || (pdj == nm && og < nmi)) {
                    nm = pdj; nmi = og; nx = p4.x; ny = p4.y; nz = p4.z;
                }
            }
            // warp argmax (pd >= 0: float bits order-isomorphic to u32)
            unsigned mb = __float_as_uint(nm);
            unsigned wm = __reduce_max_sync(FULL, mb);
            unsigned cand = (mb == wm) ? nmi : 0xffffffffu;
            unsigned wmi = __reduce_min_sync(FULL, cand);   // min ORIGINAL idx
            // broadcast winner coords from the (unique) owner lane
            unsigned obal = __ballot_sync(FULL, (mb == wm) && (nmi == wmi));
            int owner = __ffs(obal) - 1;
            cwx = __shfl_sync(FULL, nx, owner);
            cwy = __shfl_sync(FULL, ny, owner);
            cwz = __shfl_sync(FULL, nz, owner);
            wm_c = wm; wmi_c = wmi; m_wc = __uint_as_float(wm);
        }
        // lane 0 emits the (possibly cached) warp slot every iteration
        if (lane == 0) {
            s_val[buf][w] = wm_c;
            s_idx[buf][w] = wmi_c;
            s_cxyz[buf][w] = make_float4(cwx, cwy, cwz, 0.0f);
        }
        __syncthreads();

        // ---- every warp reduces the 32 slots itself (no 2nd barrier) ----
        unsigned v  = s_val[buf][lane];
        unsigned ix = s_idx[buf][lane];
        unsigned gm = __reduce_max_sync(FULL, v);
        unsigned c2 = (v == gm) ? ((ix << 5) | (unsigned)lane) : 0xffffffffu;
        unsigned pk = __reduce_min_sync(FULL, c2);        // min (idx, slot)
        g = pk >> 5;
        c = s_cxyz[buf][pk & 31u];                        // broadcast LDS.128
    }
}

// ============================================================================
// 2) KNN: K=16 smallest (d, idx) lexicographic (matches top_k(-d)).
// ============================================================================
__global__ __launch_bounds__(128)
void knn_kernel(const float* __restrict__ coords)
{
    const int b = blockIdx.y;
    const int s = blockIdx.x * 128 + threadIdx.x;
    const float* cb = coords + (size_t)b * N_ * 3;

    const int qi = g_fps_idx[b * S_ + s];
    const float qx = cb[qi * 3 + 0];
    const float qy = cb[qi * 3 + 1];
    const float qz = cb[qi * 3 + 2];

    __shared__ float4 tile[2048];     // 32 KB, padded xyz

    float dk[K_];
    int   ik[K_];
#pragma unroll
    for (int j = 0; j < K_; j++) { dk[j] = CUDART_INF_F; ik[j] = 0; }

    for (int t0 = 0; t0 < N_; t0 += 2048) {
        __syncthreads();
        for (int v = threadIdx.x; v < 2048; v += 128) {
            int p = t0 + v;
            tile[v] = make_float4(cb[p * 3 + 0], cb[p * 3 + 1], cb[p * 3 + 2], 0.0f);
        }
        __syncthreads();

#pragma unroll 8
        for (int p = 0; p < 2048; p++) {
            float4 cc = tile[p];
            float dx = __fsub_rn(qx, cc.x);
            float dy = __fsub_rn(qy, cc.y);
            float dz = __fsub_rn(qz, cc.z);
            float dd = __fadd_rn(__fadd_rn(__fmul_rn(dx, dx), __fmul_rn(dy, dy)),
                                 __fmul_rn(dz, dz));
            if (dd < dk[K_ - 1]) {
                float vd = dd; int vi = t0 + p;
#pragma unroll
                for (int j = 0; j < K_; j++) {
                    if (vd < dk[j]) {
                        float td = dk[j]; int ti2 = ik[j];
                        dk[j] = vd; ik[j] = vi;
                        vd = td; vi = ti2;
                    }
                }
            }
        }
    }

    int* out = &g_knn_idx[((size_t)b * S_ + s) * K_];
#pragma unroll
    for (int j = 0; j < K_; j++) out[j] = ik[j];
}

// ============================================================================
// 3) Pointwise MLP (64->128) + BN(eval) + ReLU on ALL points -> g_h.
// ============================================================================
__global__ __launch_bounds__(256)
void mlp_kernel(const float* __restrict__ features,
                const float* __restrict__ W,
                const float* __restrict__ bias,
                const float* __restrict__ gamma,
                const float* __restrict__ beta,
                const float* __restrict__ rmean,
                const float* __restrict__ rvar)
{
    const int pt0  = blockIdx.x * 32;
    const int o    = threadIdx.x & 127;
    const int half = threadIdx.x >> 7;

    __shared__ float sW[DOUT_ * DIN_];          // 32 KB
    __shared__ float sF[32 * DIN_];             // 8 KB

    for (int v = threadIdx.x; v < DOUT_ * DIN_; v += 256) sW[v] = W[v];
    for (int v = threadIdx.x; v < 32 * DIN_;   v += 256) sF[v] = features[(size_t)pt0 * DIN_ + v];
    __syncthreads();

    float w[DIN_];
#pragma unroll
    for (int d = 0; d < DIN_; d++) w[d] = sW[o * DIN_ + d];

    const float bo = bias[o];
    const float mn = rmean[o];
    const float sc = gamma[o] * rsqrtf(rvar[o] + BN_EPS_);
    const float bt = beta[o];

    for (int p = half * 16; p < half * 16 + 16; p++) {
        float acc = 0.0f;
#pragma unroll
        for (int d = 0; d < DIN_; d += 4) {
            float4 ff = *(const float4*)&sF[p * DIN_ + d];
            acc = fmaf(w[d + 0], ff.x, acc);
            acc = fmaf(w[d + 1], ff.y, acc);
            acc = fmaf(w[d + 2], ff.z, acc);
            acc = fmaf(w[d + 3], ff.w, acc);
        }
        float lin = acc + bo;
        float val = (lin - mn) * sc + bt;
        g_h[((size_t)pt0 + p) * DOUT_ + o] = fmaxf(val, 0.0f);
    }
}

// ============================================================================
// 4) Gather K neighbors' features + max-pool (two launches).
// ============================================================================
__global__ __launch_bounds__(256)
void pool_kernel(float* __restrict__ out_feat, int b0)
{
    const int b   = b0 + blockIdx.y;
    const int s   = blockIdx.x * 8 + (threadIdx.x >> 5);
    const int col = threadIdx.x & 31;

    const int* kid = &g_knn_idx[((size_t)b * S_ + s) * K_];

    float4 acc = make_float4(-CUDART_INF_F, -CUDART_INF_F, -CUDART_INF_F, -CUDART_INF_F);
#pragma unroll
    for (int k = 0; k < K_; k++) {
        const int id = kid[k];
        const float4 v = *(const float4*)&g_h[((size_t)b * N_ + id) * DOUT_ + col * 4];
        acc.x = fmaxf(acc.x, v.x);
        acc.y = fmaxf(acc.y, v.y);
        acc.z = fmaxf(acc.z, v.z);
        acc.w = fmaxf(acc.w, v.w);
    }
    *(float4*)&out_feat[((size_t)b * S_ + s) * DOUT_ + col * 4] = acc;
}

// ============================================================================
extern "C" void kernel_launch(void* const* d_in, const int* in_sizes, int n_in,
                              void* d_out, int out_size)
{
    const float* coords   = (const float*)d_in[0];
    const float* features = (const float*)d_in[1];
    const float* W        = (const float*)d_in[2];
    const float* bias     = (const float*)d_in[3];
    const float* gamma    = (const float*)d_in[4];
    const float* beta     = (const float*)d_in[5];
    const float* rmean    = (const float*)d_in[6];
    const float* rvar     = (const float*)d_in[7];

    float* out        = (float*)d_out;
    float* out_coords = out;                       // [B, S, 3]
    float* out_feat   = out + (size_t)B_ * S_ * 3; // [B, S, 128]

    const int fps_dyn_bytes = N_ * (int)sizeof(float4);
    static bool attr_done = false;
    if (!attr_done) {
        cudaFuncSetAttribute(fps_kernel, cudaFuncAttributeMaxDynamicSharedMemorySize,
                             fps_dyn_bytes);
        attr_done = true;
    }

    fps_kernel<<<B_, FT_, fps_dyn_bytes>>>(coords, out_coords);
    mlp_kernel<<<(B_ * N_) / 32, 256>>>(features, W, bias, gamma, beta, rmean, rvar);
    knn_kernel<<<dim3(S_ / 128, B_), 128>>>(coords);
    pool_kernel<<<dim3(S_ / 8, 4), 256>>>(out_feat, 0);
    pool_kernel<<<dim3(S_ / 8, 4), 256>>>(out_feat, 4);
}

// round 12
// speedup vs baseline: 2.1058x; 2.1058x over previous
#include <cuda_runtime.h>
#include <cuda_bf16.h>
#include <math_constants.h>

#define B_      8
#define N_      8192
#define S_      2048
#define K_      16
#define DIN_    64
#define DOUT_   128
#define BN_EPS_ 1e-5f

#define FT_     512            // FPS threads (16 warps)
#define PPT_    16             // points per thread (Morton-contiguous)
#define NCELL_  4096           // 16x16x16 spatial cells, Morton-ordered

// ---------------- scratch (static __device__ — no allocation allowed) ----------------
__device__ int   g_fps_idx[B_ * S_];
__device__ int   g_knn_idx[B_ * S_ * K_];
__device__ float g_h[B_ * N_ * DOUT_];   // 33.5 MB, post MLP+BN+ReLU features

// ---------------- packed f32x2 helpers (exact IEEE per lane) ----------------
__device__ __forceinline__ unsigned long long pack2(float lo, float hi) {
    unsigned long long r;
    asm("mov.b64 %0, {%1, %2};" : "=l"(r) : "f"(lo), "f"(hi));
    return r;
}
__device__ __forceinline__ void unpack2(unsigned long long v, float& lo, float& hi) {
    asm("mov.b64 {%0, %1}, %2;" : "=f"(lo), "=f"(hi) : "l"(v));
}
__device__ __forceinline__ unsigned long long add2(unsigned long long a, unsigned long long b) {
    unsigned long long r;
    asm("add.rn.f32x2 %0, %1, %2;" : "=l"(r) : "l"(a), "l"(b));
    return r;
}
__device__ __forceinline__ unsigned long long mul2(unsigned long long a, unsigned long long b) {
    unsigned long long r;
    asm("mul.rn.f32x2 %0, %1, %2;" : "=l"(r) : "l"(a), "l"(b));
    return r;
}
// 4-bit Morton spread: bits -> positions 0,3,6,9 (setup only)
__device__ __forceinline__ unsigned spread3(unsigned v) {
    return (v & 1u) | ((v & 2u) << 2) | ((v & 4u) << 4) | ((v & 8u) << 6);
}

// ============================================================================
// 1) FPS — one CTA per batch, 512 threads x 16 Morton-contiguous points in
//    NEGATED packed-f32x2 REGISTERS ((-p)+c == -(p-c) bit-exactly; squaring
//    erases the sign). Per-thread register bbox over its compact Morton block.
//    Iteration (one barrier, double-buffered slots):
//      - per-thread bound: lb(c,bbox)*0.99999 >= m (cached max pd) => update
//        provably a bit-exact no-op -> skip compute, reuse cached (m, mi).
//      - else 64 packed FP ops (exact IEEE order), 16 mins, exact argmax with
//        ORIGINAL-index tie-break (== jnp.argmax).
//      - warp REDUX (max pd-bits, tie -> min orig idx); unique owner lane
//        writes (val, idx, coords via ONE LDS.128) to its warp slot.
//      - BAR; every warp reduces the 32 slots (dummies for 16..31);
//        cross-warp tie via packed (idx<<5|slot) REDUX-min; coords: 1 LDS.128.
//    Hot loop has NO strided smem reads -> no bank conflicts.
// ============================================================================
extern __shared__ float4 s_sort[];   // [N_] Morton-sorted coords, orig idx in .w

__global__ __launch_bounds__(FT_, 1)
void fps_kernel(const float* __restrict__ coords, float* __restrict__ out_coords)
{
    __shared__ unsigned s_hist[NCELL_];          // 16 KB
    __shared__ unsigned s_wsum[32];
    __shared__ unsigned s_val[2][32];
    __shared__ unsigned s_idx[2][32];
    __shared__ float4   s_cxyz[2][32];

    const int b    = blockIdx.x;
    const int t    = threadIdx.x;
    const int lane = t & 31;
    const int w    = t >> 5;
    const unsigned FULL = 0xffffffffu;
    const float* cb = coords + (size_t)b * N_ * 3;

    // ---------------- setup: Morton counting sort ----------------
    for (int v = t; v < NCELL_; v += FT_) s_hist[v] = 0u;
    // dummy reduce slots for warp lanes 16..31 (only 16 real warps)
    if (t >= 16 && t < 32) {
        s_val[0][t] = 0u;        s_val[1][t] = 0u;
        s_idx[0][t] = 0xFFFFFFu; s_idx[1][t] = 0xFFFFFFu;   // (idx<<5) safe
    }
    __syncthreads();

    float fv[48];
    unsigned cells[PPT_];
    {
        const float4* src = (const float4*)(cb + t * 48);   // points 16t..16t+15
#pragma unroll
        for (int q = 0; q < 12; q++) {
            float4 v = src[q];
            fv[q * 4 + 0] = v.x; fv[q * 4 + 1] = v.y; fv[q * 4 + 2] = v.z; fv[q * 4 + 3] = v.w;
        }
#pragma unroll
        for (int j = 0; j < PPT_; j++) {
            unsigned bx = (unsigned)min(max((int)floorf(fv[3 * j + 0] * 2.0f) + 8, 0), 15);
            unsigned by = (unsigned)min(max((int)floorf(fv[3 * j + 1] * 2.0f) + 8, 0), 15);
            unsigned bz = (unsigned)min(max((int)floorf(fv[3 * j + 2] * 2.0f) + 8, 0), 15);
            cells[j] = spread3(bx) | (spread3(by) << 1) | (spread3(bz) << 2);
            atomicAdd(&s_hist[cells[j]], 1u);
        }
    }
    __syncthreads();
    // parallel exclusive scan of 4096 counters (each thread owns 8)
    {
        unsigned a[8];
#pragma unroll
        for (int k = 0; k < 8; k++) a[k] = s_hist[t * 8 + k];
        unsigned tot = 0;
#pragma unroll
        for (int k = 0; k < 8; k++) tot += a[k];
        unsigned inc = tot;
#pragma unroll
        for (int off = 1; off < 32; off <<= 1) {
            unsigned u = __shfl_up_sync(FULL, inc, off);
            if (lane >= off) inc += u;
        }
        if (lane == 31) s_wsum[w] = inc;
        unsigned exl = inc - tot;
        __syncthreads();
        if (t < 32) {
            unsigned v = (t < 16) ? s_wsum[t] : 0u;
            unsigned i2 = v;
#pragma unroll
            for (int off = 1; off < 32; off <<= 1) {
                unsigned u = __shfl_up_sync(FULL, i2, off);
                if (lane >= off) i2 += u;
            }
            if (t < 16) s_wsum[t] = i2 - v;
        }
        __syncthreads();
        unsigned run = s_wsum[w] + exl;
#pragma unroll
        for (int k = 0; k < 8; k++) { s_hist[t * 8 + k] = run; run += a[k]; }
    }
    __syncthreads();
#pragma unroll
    for (int j = 0; j < PPT_; j++) {
        unsigned dst = atomicAdd(&s_hist[cells[j]], 1u);
        unsigned orig = (unsigned)(t * PPT_ + j);
        s_sort[dst] = make_float4(fv[3 * j], fv[3 * j + 1], fv[3 * j + 2],
                                  __uint_as_float(orig));
    }
    __syncthreads();

    // ---- pull my 16 Morton-sorted points into registers + bbox ----
    unsigned long long npx[8], npy[8], npz[8];
    unsigned ogr[PPT_];
    float pd[PPT_];
    float bmnx = CUDART_INF_F, bmny = CUDART_INF_F, bmnz = CUDART_INF_F;
    float bmxx = -CUDART_INF_F, bmxy = -CUDART_INF_F, bmxz = -CUDART_INF_F;
    {
        const int base = t * PPT_;
        float sx[PPT_], sy[PPT_], sz[PPT_];
#pragma unroll
        for (int j = 0; j < PPT_; j++) {
            float4 p4 = s_sort[base + j];
            sx[j] = p4.x; sy[j] = p4.y; sz[j] = p4.z;
            bmnx = fminf(bmnx, p4.x); bmxx = fmaxf(bmxx, p4.x);
            bmny = fminf(bmny, p4.y); bmxy = fmaxf(bmxy, p4.y);
            bmnz = fminf(bmnz, p4.z); bmxz = fmaxf(bmxz, p4.z);
            pd[j] = 1e10f;
            ogr[j] = __float_as_uint(p4.w);
        }
#pragma unroll
        for (int jj = 0; jj < 8; jj++) {
            npx[jj] = pack2(-sx[2 * jj], -sx[2 * jj + 1]);
            npy[jj] = pack2(-sy[2 * jj], -sy[2 * jj + 1]);
            npz[jj] = pack2(-sz[2 * jj], -sz[2 * jj + 1]);
        }
    }

    float    m   = CUDART_INF_F;       // cached max_j pd[j] (forces 1st compute)
    unsigned mi  = 0xffffffffu;        // cached argmax original index
    int      msp = t * PPT_;           // cached argmax sorted slot

    unsigned g = 0u;
    float4 c = make_float4(cb[0], cb[1], cb[2], 0.0f);   // start at point 0

    for (int i = 0; i < S_; i++) {
        if (t == 0) {
            g_fps_idx[b * S_ + i] = (int)g;
            float* oc = out_coords + ((size_t)b * S_ + i) * 3;
            oc[0] = c.x; oc[1] = c.y; oc[2] = c.z;
        }
        if (i == S_ - 1) break;
        const int buf = i & 1;

        // ---- per-thread bound: skip iff provably a bit-exact no-op ----
        float ax = fmaxf(fmaxf(__fsub_rn(bmnx, c.x), __fsub_rn(c.x, bmxx)), 0.0f);
        float ay = fmaxf(fmaxf(__fsub_rn(bmny, c.y), __fsub_rn(c.y, bmxy)), 0.0f);
        float az = fmaxf(fmaxf(__fsub_rn(bmnz, c.z), __fsub_rn(c.z, bmxz)), 0.0f);
        float lb = ax * ax + ay * ay + az * az;

        if (!(lb * 0.99999f >= m)) {
            // packed recompute: exact IEEE (-p)+c, mul, ((x+y)+z)
            const unsigned long long cxx = pack2(c.x, c.x);
            const unsigned long long cyy = pack2(c.y, c.y);
            const unsigned long long czz = pack2(c.z, c.z);
#pragma unroll
            for (int jj = 0; jj < 8; jj++) {
                unsigned long long dx = add2(npx[jj], cxx);
                unsigned long long dy = add2(npy[jj], cyy);
                unsigned long long dz = add2(npz[jj], czz);
                unsigned long long dd = add2(add2(mul2(dx, dx), mul2(dy, dy)), mul2(dz, dz));
                float d0, d1;
                unpack2(dd, d0, d1);
                pd[2 * jj]     = fminf(pd[2 * jj],     d0);
                pd[2 * jj + 1] = fminf(pd[2 * jj + 1], d1);
            }
            // exact argmax: value tree, then min-orig among equal maxima
            float vm = pd[0];
#pragma unroll
            for (int j = 1; j < PPT_; j++) vm = fmaxf(vm, pd[j]);
            unsigned nmi = 0xffffffffu; int nj = 0;
#pragma unroll
            for (int j = 0; j < PPT_; j++)
                if (pd[j] == vm && ogr[j] < nmi) { nmi = ogr[j]; nj = j; }
            m = vm; mi = nmi; msp = t * PPT_ + nj;
        }

        // ---- warp argmax (pd >= 0: float bits order-isomorphic to u32) ----
        unsigned mb = __float_as_uint(m);
        unsigned wm = __reduce_max_sync(FULL, mb);
        unsigned cand = (mb == wm) ? mi : 0xffffffffu;
        unsigned wmi = __reduce_min_sync(FULL, cand);     // min ORIGINAL index
        if (mb == wm && mi == wmi) {                      // unique owner lane
            s_val[buf][w] = wm;
            s_idx[buf][w] = wmi;
            s_cxyz[buf][w] = s_sort[msp];                 // owner-only LDS.128
        }
        __syncthreads();

        // ---- every warp reduces the 32 slots itself (no 2nd barrier) ----
        unsigned v  = s_val[buf][lane];
        unsigned ix = s_idx[buf][lane];
        unsigned gm = __reduce_max_sync(FULL, v);
        unsigned c2 = (v == gm) ? ((ix << 5) | (unsigned)lane) : 0xffffffffu;
        unsigned pk = __reduce_min_sync(FULL, c2);        // min (idx, slot)
        g = pk >> 5;
        c = s_cxyz[buf][pk & 31u];                        // broadcast LDS.128
    }
}

// ============================================================================
// 2) KNN: K=16 smallest (d, idx) lexicographic (matches top_k(-d)).
// ============================================================================
__global__ __launch_bounds__(128)
void knn_kernel(const float* __restrict__ coords)
{
    const int b = blockIdx.y;
    const int s = blockIdx.x * 128 + threadIdx.x;
    const float* cb = coords + (size_t)b * N_ * 3;

    const int qi = g_fps_idx[b * S_ + s];
    const float qx = cb[qi * 3 + 0];
    const float qy = cb[qi * 3 + 1];
    const float qz = cb[qi * 3 + 2];

    __shared__ float4 tile[2048];     // 32 KB, padded xyz

    float dk[K_];
    int   ik[K_];
#pragma unroll
    for (int j = 0; j < K_; j++) { dk[j] = CUDART_INF_F; ik[j] = 0; }

    for (int t0 = 0; t0 < N_; t0 += 2048) {
        __syncthreads();
        for (int v = threadIdx.x; v < 2048; v += 128) {
            int p = t0 + v;
            tile[v] = make_float4(cb[p * 3 + 0], cb[p * 3 + 1], cb[p * 3 + 2], 0.0f);
        }
        __syncthreads();

#pragma unroll 8
        for (int p = 0; p < 2048; p++) {
            float4 cc = tile[p];
            float dx = __fsub_rn(qx, cc.x);
            float dy = __fsub_rn(qy, cc.y);
            float dz = __fsub_rn(qz, cc.z);
            float dd = __fadd_rn(__fadd_rn(__fmul_rn(dx, dx), __fmul_rn(dy, dy)),
                                 __fmul_rn(dz, dz));
            if (dd < dk[K_ - 1]) {
                float vd = dd; int vi = t0 + p;
#pragma unroll
                for (int j = 0; j < K_; j++) {
                    if (vd < dk[j]) {
                        float td = dk[j]; int ti2 = ik[j];
                        dk[j] = vd; ik[j] = vi;
                        vd = td; vi = ti2;
                    }
                }
            }
        }
    }

    int* out = &g_knn_idx[((size_t)b * S_ + s) * K_];
#pragma unroll
    for (int j = 0; j < K_; j++) out[j] = ik[j];
}

// ============================================================================
// 3) Pointwise MLP (64->128) + BN(eval) + ReLU on ALL points -> g_h.
// ============================================================================
__global__ __launch_bounds__(256)
void mlp_kernel(const float* __restrict__ features,
                const float* __restrict__ W,
                const float* __restrict__ bias,
                const float* __restrict__ gamma,
                const float* __restrict__ beta,
                const float* __restrict__ rmean,
                const float* __restrict__ rvar)
{
    const int pt0  = blockIdx.x * 32;
    const int o    = threadIdx.x & 127;
    const int half = threadIdx.x >> 7;

    __shared__ float sW[DOUT_ * DIN_];          // 32 KB
    __shared__ float sF[32 * DIN_];             // 8 KB

    for (int v = threadIdx.x; v < DOUT_ * DIN_; v += 256) sW[v] = W[v];
    for (int v = threadIdx.x; v < 32 * DIN_;   v += 256) sF[v] = features[(size_t)pt0 * DIN_ + v];
    __syncthreads();

    float w[DIN_];
#pragma unroll
    for (int d = 0; d < DIN_; d++) w[d] = sW[o * DIN_ + d];

    const float bo = bias[o];
    const float mn = rmean[o];
    const float sc = gamma[o] * rsqrtf(rvar[o] + BN_EPS_);
    const float bt = beta[o];

    for (int p = half * 16; p < half * 16 + 16; p++) {
        float acc = 0.0f;
#pragma unroll
        for (int d = 0; d < DIN_; d += 4) {
            float4 ff = *(const float4*)&sF[p * DIN_ + d];
            acc = fmaf(w[d + 0], ff.x, acc);
            acc = fmaf(w[d + 1], ff.y, acc);
            acc = fmaf(w[d + 2], ff.z, acc);
            acc = fmaf(w[d + 3], ff.w, acc);
        }
        float lin = acc + bo;
        float val = (lin - mn) * sc + bt;
        g_h[((size_t)pt0 + p) * DOUT_ + o] = fmaxf(val, 0.0f);
    }
}

// ============================================================================
// 4) Gather K neighbors' features + max-pool (two launches).
// ============================================================================
__global__ __launch_bounds__(256)
void pool_kernel(float* __restrict__ out_feat, int b0)
{
    const int b   = b0 + blockIdx.y;
    const int s   = blockIdx.x * 8 + (threadIdx.x >> 5);
    const int col = threadIdx.x & 31;

    const int* kid = &g_knn_idx[((size_t)b * S_ + s) * K_];

    float4 acc = make_float4(-CUDART_INF_F, -CUDART_INF_F, -CUDART_INF_F, -CUDART_INF_F);
#pragma unroll
    for (int k = 0; k < K_; k++) {
        const int id = kid[k];
        const float4 v = *(const float4*)&g_h[((size_t)b * N_ + id) * DOUT_ + col * 4];
        acc.x = fmaxf(acc.x, v.x);
        acc.y = fmaxf(acc.y, v.y);
        acc.z = fmaxf(acc.z, v.z);
        acc.w = fmaxf(acc.w, v.w);
    }
    *(float4*)&out_feat[((size_t)b * S_ + s) * DOUT_ + col * 4] = acc;
}

// ============================================================================
extern "C" void kernel_launch(void* const* d_in, const int* in_sizes, int n_in,
                              void* d_out, int out_size)
{
    const float* coords   = (const float*)d_in[0];
    const float* features = (const float*)d_in[1];
    const float* W        = (const float*)d_in[2];
    const float* bias     = (const float*)d_in[3];
    const float* gamma    = (const float*)d_in[4];
    const float* beta     = (const float*)d_in[5];
    const float* rmean    = (const float*)d_in[6];
    const float* rvar     = (const float*)d_in[7];

    float* out        = (float*)d_out;
    float* out_coords = out;                       // [B, S, 3]
    float* out_feat   = out + (size_t)B_ * S_ * 3; // [B, S, 128]

    const int fps_dyn_bytes = N_ * (int)sizeof(float4);
    static bool attr_done = false;
    if (!attr_done) {
        cudaFuncSetAttribute(fps_kernel, cudaFuncAttributeMaxDynamicSharedMemorySize,
                             fps_dyn_bytes);
        attr_done = true;
    }

    fps_kernel<<<B_, FT_, fps_dyn_bytes>>>(coords, out_coords);
    mlp_kernel<<<(B_ * N_) / 32, 256>>>(features, W, bias, gamma, beta, rmean, rvar);
    knn_kernel<<<dim3(S_ / 128, B_), 128>>>(coords);
    pool_kernel<<<dim3(S_ / 8, 4), 256>>>(out_feat, 0);
    pool_kernel<<<dim3(S_ / 8, 4), 256>>>(out_feat, 4);
}